// round 15
// baseline (speedup 1.0000x reference)
#include <cuda_runtime.h>
#include <cuda_bf16.h>
#include <stdint.h>
#include <cstdint>
#include <math.h>

#define N_NODES 50000
#define N_EDGES 1600000
#define C 128
#define KK 25            // 5x5 spline slots
#define KEXT 26          // + root slot
#define GK (KEXT * C)    // 3328
#define BN_EPS 1e-5f

// ---------------- device scratch (allocation-free: static globals) ----------------
__device__ float  g_h[(size_t)N_NODES * C];       // layer-0 input (embedded)
__device__ float  g_hpre[(size_t)N_NODES * C];    // pre-BN conv output
__device__ __nv_bfloat16 g_Ghi[(size_t)N_NODES * GK];  // gathered features hi plane
__device__ __nv_bfloat16 g_Glo[(size_t)N_NODES * GK];  // lo plane
__device__ int    g_src32[N_EDGES];
__device__ int    g_dst32[N_EDGES];
__device__ int    g_cnt[N_NODES];                 // node totals (k_sumcells -> k_scan)
__device__ int    g_cnt2[N_NODES * 16];           // per (node,cell); zero at load,
                                                  // re-zeroed by k_cursors each call
__device__ int    g_rowptr[N_NODES + 1];
__device__ int    g_cursor2[N_NODES * 16];        // post-scatter: per-cell END offsets
__device__ int    g_csr_src[N_EDGES];
__device__ float4 g_csr_w[N_EDGES];
__device__ float  g_bnsum[3][C], g_bnsq[3][C];    // per-layer stats (zeroed in setup)
__device__ float  g_bna[C], g_bnb[C];             // current-layer affine
__device__ float  g_wt[C * C];                    // final_w transposed
// Pre-transposed + hi/lo split conv weights: [L][n][k] K-major bf16
__device__ __nv_bfloat16 g_wt_hi[3ull * C * GK];
__device__ __nv_bfloat16 g_wt_lo[3ull * C * GK];

__device__ __forceinline__ unsigned smem_u32(const void* p) {
    unsigned a;
    asm("{ .reg .u64 t; cvta.to.shared.u64 t, %1; cvt.u32.u64 %0, t; }" : "=r"(a) : "l"(p));
    return a;
}

// ---------------- fused setup: detect + embed + convert + cell-hist + prepack ----
__global__ void k_setup(const void* xp, const float* __restrict__ emb,
                        const void* eip, const float* __restrict__ attr,
                        const float* __restrict__ cw, const float* __restrict__ cr,
                        const float* __restrict__ fw) {
    int i = blockIdx.x * blockDim.x + threadIdx.x;

    // inline int64-vs-int32 detection (warp-uniform, L1-resident loads)
    int flag;
    {
        const int* e32 = (const int*)eip;
        int lane = threadIdx.x & 31;
        int z = 1;
        #pragma unroll
        for (int q = 0; q < 4; q++)
            if (e32[2 * (lane + q * 32) + 1] != 0) z = 0;
        flag = __all_sync(0xffffffffu, z);   // 1 => int64 indices
    }

    // h0 = emb[x]  (i < 6.4M dominates the grid)
    if (i < N_NODES * C) {
        int n = i >> 7, c = i & 127;
        int xv = flag ? (int)((const long long*)xp)[n] : ((const int*)xp)[n];
        g_h[i] = emb[xv * C + c];
    }
    // edge index conversion + (node,cell) histogram (g_cnt2 is zero at entry)
    if (i < N_EDGES) {
        int s, d;
        if (flag) {
            s = (int)((const long long*)eip)[i];
            d = (int)((const long long*)eip)[N_EDGES + i];
        } else {
            s = ((const int*)eip)[i];
            d = ((const int*)eip)[N_EDGES + i];
        }
        g_src32[i] = s;
        g_dst32[i] = d;
        float v0 = attr[2 * i] * 4.0f;
        float v1 = attr[2 * i + 1] * 4.0f;
        int l0 = (int)fminf(fmaxf(floorf(v0), 0.0f), 3.0f);
        int l1 = (int)fminf(fmaxf(floorf(v1), 0.0f), 3.0f);
        atomicAdd(&g_cnt2[d * 16 + l0 + 4 * l1], 1);
    }
    // zero BN stats
    if (i < 3 * C) { g_bnsum[i / C][i % C] = 0.0f; g_bnsq[i / C][i % C] = 0.0f; }
    // final_w transpose
    if (i < C * C) {
        int k = i >> 7, o = i & 127;
        g_wt[k * C + o] = fw[o * C + k];
    }
    // conv weight prepack: transpose + hi/lo bf16 split
    if (i < 3 * GK * C) {
        int L = i / (GK * C);
        int rem = i - L * (GK * C);
        int n = rem / GK;
        int k = rem - n * GK;
        float v = (k < KK * C) ? cw[(size_t)L * KK * C * C + (size_t)k * C + n]
                               : cr[(size_t)L * C * C + (size_t)(k - KK * C) * C + n];
        __nv_bfloat16 h = __float2bfloat16(v);
        __nv_bfloat16 l = __float2bfloat16(v - __bfloat162float(h));
        size_t o = (size_t)L * C * GK + (size_t)n * GK + k;
        g_wt_hi[o] = h;
        g_wt_lo[o] = l;
    }
}

// ---------------- parallel: node totals from 16-cell histogram ----------------
__global__ void k_sumcells() {
    int n = blockIdx.x * blockDim.x + threadIdx.x;
    if (n >= N_NODES) return;
    const int4* p = (const int4*)&g_cnt2[n * 16];
    int v = 0;
    #pragma unroll
    for (int q = 0; q < 4; q++) {
        int4 c4 = p[q];
        v += c4.x + c4.y + c4.z + c4.w;
    }
    g_cnt[n] = v;
}

// ---------------- CSR scan over node totals (single block); re-zeroes g_cnt ----
__global__ void k_scan() {  // single block, 1024 threads
    __shared__ int wsum[32];
    __shared__ int carry;
    int t = threadIdx.x;
    if (t == 0) carry = 0;
    __syncthreads();
    const int nchunks = (N_NODES + 1023) / 1024;
    for (int ch = 0; ch < nchunks; ch++) {
        int i = ch * 1024 + t;
        int v = 0;
        if (i < N_NODES) { v = g_cnt[i]; g_cnt[i] = 0; }
        int x = v;
        #pragma unroll
        for (int o = 1; o < 32; o <<= 1) {
            int y = __shfl_up_sync(0xffffffffu, x, o);
            if ((t & 31) >= o) x += y;
        }
        if ((t & 31) == 31) wsum[t >> 5] = x;
        __syncthreads();
        if (t < 32) {
            int w = wsum[t], xw = w;
            #pragma unroll
            for (int o = 1; o < 32; o <<= 1) {
                int y = __shfl_up_sync(0xffffffffu, xw, o);
                if (t >= o) xw += y;
            }
            wsum[t] = xw - w;  // exclusive warp offsets
        }
        __syncthreads();
        int incl = x + wsum[t >> 5] + carry;
        if (i < N_NODES) g_rowptr[i] = incl - v;
        __syncthreads();
        if (t == 1023) carry = incl;
        __syncthreads();
    }
    if (t == 0) g_rowptr[N_NODES] = carry;
}

// ---------------- parallel: per-node cell cursors; re-zeroes g_cnt2 ------------
__global__ void k_cursors() {
    int n = blockIdx.x * blockDim.x + threadIdx.x;
    if (n >= N_NODES) return;
    int base = g_rowptr[n];
    #pragma unroll
    for (int cell = 0; cell < 16; cell++) {
        int idx = n * 16 + cell;
        int cnt = g_cnt2[idx];
        g_cursor2[idx] = base;
        base += cnt;
        g_cnt2[idx] = 0;
    }
}

__global__ void k_scatter(const float* __restrict__ attr) {
    int e = blockIdx.x * blockDim.x + threadIdx.x;
    if (e >= N_EDGES) return;
    int d = g_dst32[e];
    float v0 = attr[2 * e] * 4.0f;
    float v1 = attr[2 * e + 1] * 4.0f;
    float l0 = fminf(fmaxf(floorf(v0), 0.0f), 3.0f);
    float l1 = fminf(fmaxf(floorf(v1), 0.0f), 3.0f);
    float f0 = v0 - l0, f1 = v1 - l1;
    int cell = (int)l0 + 4 * (int)l1;
    int pos = atomicAdd(&g_cursor2[d * 16 + cell], 1);
    g_csr_src[pos] = g_src32[e];
    float w00 = (1.0f - f0) * (1.0f - f1);
    float w10 = f0 * (1.0f - f1);
    float w01 = (1.0f - f0) * f1;
    float w11 = f0 * f1;
    g_csr_w[pos] = make_float4(w00, w10, w01, w11);
    // after this kernel, g_cursor2[n*16+cell] == END offset of that cell's range
}

// ---------------- aggregation: cell-sorted edges, 25 REGISTER accumulators ------
// No shared memory: cells unrolled statically, corner ids are compile-time.
__global__ void __launch_bounds__(128, 8) k_aggregate(int use_bn, int relu) {
    const int n = blockIdx.x;
    const int c = threadIdx.x;

    float a = 1.0f, b = 0.0f;
    const float* in = g_h;
    if (use_bn) { a = g_bna[c]; b = g_bnb[c]; in = g_hpre; }

    float acc[KK];
    #pragma unroll
    for (int k = 0; k < KK; k++) acc[k] = 0.0f;

    const int rs = g_rowptr[n];
    const int re = g_rowptr[n + 1];
    int cs = rs;
    #pragma unroll
    for (int cell = 0; cell < 16; cell++) {
        const int ce = g_cursor2[n * 16 + cell];   // end offset of this cell's run
        float r0 = 0.f, r1 = 0.f, r2 = 0.f, r3 = 0.f;
        for (int e = cs; e < ce; e++) {
            int s = g_csr_src[e];
            float4 w = g_csr_w[e];
            float hv = a * in[(size_t)s * C + c] + b;
            if (relu) hv = fmaxf(hv, 0.0f);
            r0 += w.x * hv;
            r1 += w.y * hv;
            r2 += w.z * hv;
            r3 += w.w * hv;
        }
        const int base = (cell & 3) + 5 * (cell >> 2);   // compile-time constant
        acc[base]     += r0;
        acc[base + 1] += r1;
        acc[base + 5] += r2;
        acc[base + 6] += r3;
        cs = ce;
    }

    const float invd = 1.0f / fmaxf((float)(re - rs), 1.0f);
    const size_t gb = (size_t)n * GK;
    #pragma unroll
    for (int k = 0; k < KK; k++) {
        float v = acc[k] * invd;
        __nv_bfloat16 h = __float2bfloat16(v);
        g_Ghi[gb + k * C + c] = h;
        g_Glo[gb + k * C + c] = __float2bfloat16(v - __bfloat162float(h));
    }
    {
        float v = a * in[(size_t)n * C + c] + b;
        if (relu) v = fmaxf(v, 0.0f);
        __nv_bfloat16 h = __float2bfloat16(v);
        g_Ghi[gb + KK * C + c] = h;
        g_Glo[gb + KK * C + c] = __float2bfloat16(v - __bfloat162float(h));
    }
}

// ================= mma.sync bf16 hi/lo GEMM, cp.async 2-stage, fused BN stats ====
#define KCH 32                // K per chunk (bf16 elems)
#define NCH (GK / KCH)        // 104
#define SAS 40                // smem row stride in bf16 (80B)
#define PLANE (128 * SAS * 2) // 10240 B per plane
#define STAGE (4 * PLANE)     // Ah, Al, Bh, Bl
#define MMA_SMEM (2 * STAGE)  // 81920 B

__device__ __forceinline__ void cp16(unsigned dst, const void* src, int srcsize) {
    asm volatile("cp.async.cg.shared.global [%0], [%1], 16, %2;"
                 :: "r"(dst), "l"(src), "r"(srcsize) : "memory");
}
__device__ __forceinline__ void ldmx4(unsigned addr, unsigned* r) {
    asm volatile("ldmatrix.sync.aligned.m8n8.x4.shared.b16 {%0,%1,%2,%3}, [%4];"
                 : "=r"(r[0]), "=r"(r[1]), "=r"(r[2]), "=r"(r[3]) : "r"(addr));
}
__device__ __forceinline__ void mma16816(float* c, const unsigned* a,
                                         unsigned b0, unsigned b1) {
    asm volatile(
        "mma.sync.aligned.m16n8k16.row.col.f32.bf16.bf16.f32 "
        "{%0,%1,%2,%3}, {%4,%5,%6,%7}, {%8,%9}, {%0,%1,%2,%3};"
        : "+f"(c[0]), "+f"(c[1]), "+f"(c[2]), "+f"(c[3])
        : "r"(a[0]), "r"(a[1]), "r"(a[2]), "r"(a[3]), "r"(b0), "r"(b1));
}

__global__ void __launch_bounds__(256, 2) k_mma(int L, const float* __restrict__ bias) {
    extern __shared__ __align__(16) char dsm[];
    __shared__ float s_sum[C], s_sq[C];
    const unsigned sbase = smem_u32(dsm);
    const int tid = threadIdx.x;
    const int lid = tid & 31;
    const int w = tid >> 5;
    const int warp_m = (w & 3) * 32;
    const int warp_n = (w >> 2) * 64;
    const int mtile = blockIdx.x * 128;
    const char* ghi = (const char*)g_Ghi;
    const char* glo = (const char*)g_Glo;
    const char* wh = (const char*)(g_wt_hi + (size_t)L * C * GK);
    const char* wl = (const char*)(g_wt_lo + (size_t)L * C * GK);

    if (tid < C) { s_sum[tid] = 0.0f; s_sq[tid] = 0.0f; }

    const int row0 = tid >> 2, seg0 = (tid & 3) * 16;
    const int segk = (tid & 3) * 8;

    float acc[2][8][4];
    #pragma unroll
    for (int mi = 0; mi < 2; mi++)
        #pragma unroll
        for (int nb = 0; nb < 8; nb++)
            #pragma unroll
            for (int q = 0; q < 4; q++) acc[mi][nb][q] = 0.0f;

    auto issue = [&](int st, int ch) {
        unsigned sb = sbase + st * STAGE;
        size_t kb = (size_t)ch * KCH * 2;
        #pragma unroll
        for (int i = 0; i < 2; i++) {
            int row = row0 + i * 64;
            int gm = mtile + row;
            int ok = (gm < N_NODES) ? 16 : 0;
            size_t abyte = (size_t)(gm < N_NODES ? gm : 0) * (GK * 2) + kb + segk * 2;
            unsigned d = sb + row * (SAS * 2) + seg0;
            cp16(d, ghi + abyte, ok);
            cp16(d + PLANE, glo + abyte, ok);
            size_t bbyte = (size_t)row * (GK * 2) + kb + segk * 2;
            cp16(d + 2 * PLANE, wh + bbyte, 16);
            cp16(d + 3 * PLANE, wl + bbyte, 16);
        }
        asm volatile("cp.async.commit_group;" ::: "memory");
    };

    issue(0, 0);

    #pragma unroll 1
    for (int ch = 0; ch < NCH; ch++) {
        if (ch + 1 < NCH) {
            issue((ch + 1) & 1, ch + 1);
            asm volatile("cp.async.wait_group 1;" ::: "memory");
        } else {
            asm volatile("cp.async.wait_group 0;" ::: "memory");
        }
        __syncthreads();

        const unsigned ab = sbase + (ch & 1) * STAGE;
        #pragma unroll
        for (int kk = 0; kk < 2; kk++) {
            unsigned ah[2][4], al[2][4];
            #pragma unroll
            for (int mi = 0; mi < 2; mi++) {
                unsigned row = warp_m + mi * 16 + ((lid >> 3) & 1) * 8 + (lid & 7);
                unsigned col = kk * 16 + ((lid >> 4) & 1) * 8;
                unsigned off = (row * SAS + col) * 2;
                ldmx4(ab + off, ah[mi]);
                ldmx4(ab + PLANE + off, al[mi]);
            }
            #pragma unroll
            for (int nbp = 0; nbp < 4; nbp++) {
                unsigned nrow = warp_n + nbp * 16 + ((lid >> 4) & 1) * 8 + (lid & 7);
                unsigned col = kk * 16 + ((lid >> 3) & 1) * 8;
                unsigned off = (nrow * SAS + col) * 2;
                unsigned bh[4], bl[4];
                ldmx4(ab + 2 * PLANE + off, bh);
                ldmx4(ab + 3 * PLANE + off, bl);
                #pragma unroll
                for (int half = 0; half < 2; half++) {
                    int nb = nbp * 2 + half;
                    #pragma unroll
                    for (int mi = 0; mi < 2; mi++) {
                        mma16816(acc[mi][nb], ah[mi], bh[half * 2], bh[half * 2 + 1]);
                        mma16816(acc[mi][nb], ah[mi], bl[half * 2], bl[half * 2 + 1]);
                        mma16816(acc[mi][nb], al[mi], bh[half * 2], bh[half * 2 + 1]);
                    }
                }
            }
        }
        __syncthreads();
    }

    // ---- epilogue: write acc + bias to g_hpre, accumulate BN stats ----
    #pragma unroll
    for (int mi = 0; mi < 2; mi++) {
        int m0 = mtile + warp_m + mi * 16 + (lid >> 2);
        bool v0 = (m0 < N_NODES), v1 = (m0 + 8 < N_NODES);
        #pragma unroll
        for (int nb = 0; nb < 8; nb++) {
            int n = warp_n + nb * 8 + 2 * (lid & 3);
            float b0 = bias[n], b1 = bias[n + 1];
            float o00 = acc[mi][nb][0] + b0, o01 = acc[mi][nb][1] + b1;
            float o10 = acc[mi][nb][2] + b0, o11 = acc[mi][nb][3] + b1;
            float s0 = 0.f, s1 = 0.f, q0 = 0.f, q1 = 0.f;
            if (v0) {
                *(float2*)(g_hpre + (size_t)m0 * C + n) = make_float2(o00, o01);
                s0 += o00; s1 += o01; q0 += o00 * o00; q1 += o01 * o01;
            }
            if (v1) {
                *(float2*)(g_hpre + (size_t)(m0 + 8) * C + n) = make_float2(o10, o11);
                s0 += o10; s1 += o11; q0 += o10 * o10; q1 += o11 * o11;
            }
            atomicAdd(&s_sum[n], s0);
            atomicAdd(&s_sum[n + 1], s1);
            atomicAdd(&s_sq[n], q0);
            atomicAdd(&s_sq[n + 1], q1);
        }
    }
    __syncthreads();
    if (tid < C) {
        atomicAdd(&g_bnsum[L][tid], s_sum[tid]);
        atomicAdd(&g_bnsq[L][tid], s_sq[tid]);
    }
}

// ---------------- fp32 GEMM (final linear): out = BN(hpre) @ wt + bias ----------
#define BMT 128
#define BKT 8
__global__ void __launch_bounds__(256) k_gemm(const float* __restrict__ bias,
                                              float* outp, int K) {
    __shared__ __align__(16) float As[BKT][BMT];
    __shared__ __align__(16) float Bs[BKT][C];
    const float* A = g_hpre;
    float* Cp = outp;

    int tid = threadIdx.x;
    int mtile = blockIdx.x * BMT;
    int tr = tid >> 4;
    int tc = tid & 15;

    float acc[8][8];
    #pragma unroll
    for (int i = 0; i < 8; i++)
        #pragma unroll
        for (int j = 0; j < 8; j++) acc[i][j] = 0.0f;

    int arow = tid >> 1;
    int akp  = (tid & 1) * 4;
    int bkb  = tid >> 5;
    int bcol = (tid & 31) * 4;

    for (int k0 = 0; k0 < K; k0 += BKT) {
        {
            float4 av = make_float4(0.f, 0.f, 0.f, 0.f);
            int gm = mtile + arow;
            if (gm < N_NODES) {
                av = *(const float4*)(A + (size_t)gm * K + k0 + akp);
                float4 a4 = *(const float4*)(g_bna + k0 + akp);
                float4 b4 = *(const float4*)(g_bnb + k0 + akp);
                av.x = a4.x * av.x + b4.x;
                av.y = a4.y * av.y + b4.y;
                av.z = a4.z * av.z + b4.z;
                av.w = a4.w * av.w + b4.w;
            }
            As[akp][arow]     = av.x;
            As[akp + 1][arow] = av.y;
            As[akp + 2][arow] = av.z;
            As[akp + 3][arow] = av.w;
        }
        {
            int kg = k0 + bkb;
            *(float4*)&Bs[bkb][bcol] = *(const float4*)(&g_wt[(size_t)kg * C] + bcol);
        }
        __syncthreads();
        #pragma unroll
        for (int kk = 0; kk < BKT; kk++) {
            float4 a0 = *(float4*)&As[kk][tr * 8];
            float4 a1 = *(float4*)&As[kk][tr * 8 + 4];
            float4 b0 = *(float4*)&Bs[kk][tc * 8];
            float4 b1 = *(float4*)&Bs[kk][tc * 8 + 4];
            float av[8] = {a0.x, a0.y, a0.z, a0.w, a1.x, a1.y, a1.z, a1.w};
            float bv[8] = {b0.x, b0.y, b0.z, b0.w, b1.x, b1.y, b1.z, b1.w};
            #pragma unroll
            for (int i = 0; i < 8; i++)
                #pragma unroll
                for (int j = 0; j < 8; j++) acc[i][j] += av[i] * bv[j];
        }
        __syncthreads();
    }

    float bv[8];
    #pragma unroll
    for (int j = 0; j < 8; j++) bv[j] = bias[tc * 8 + j];
    #pragma unroll
    for (int i = 0; i < 8; i++) {
        int gm = mtile + tr * 8 + i;
        if (gm < N_NODES) {
            float4 o0 = make_float4(acc[i][0] + bv[0], acc[i][1] + bv[1],
                                    acc[i][2] + bv[2], acc[i][3] + bv[3]);
            float4 o1 = make_float4(acc[i][4] + bv[4], acc[i][5] + bv[5],
                                    acc[i][6] + bv[6], acc[i][7] + bv[7]);
            *(float4*)(Cp + (size_t)gm * C + tc * 8)     = o0;
            *(float4*)(Cp + (size_t)gm * C + tc * 8 + 4) = o1;
        }
    }
}

// ---------------- batch norm finalize ----------------
__global__ void k_bnfin(int L, const float* __restrict__ gamma,
                        const float* __restrict__ beta) {
    int c = threadIdx.x;
    if (c >= C) return;
    float mu = g_bnsum[L][c] / (float)N_NODES;
    float var = fmaxf(g_bnsq[L][c] / (float)N_NODES - mu * mu, 0.0f);
    float a = gamma[c] * rsqrtf(var + BN_EPS);
    g_bna[c] = a;
    g_bnb[c] = beta[c] - a * mu;
}

// ---------------- launch ----------------
extern "C" void kernel_launch(void* const* d_in, const int* in_sizes, int n_in,
                              void* d_out, int out_size) {
    const void*  x     = d_in[0];
    const void*  ei    = d_in[1];
    const float* eattr = (const float*)d_in[2];
    const float* emb   = (const float*)d_in[3];
    const float* cw    = (const float*)d_in[4];   // [3,25,128,128]
    const float* cr    = (const float*)d_in[5];   // [3,128,128]
    const float* cb    = (const float*)d_in[6];   // [3,128]
    const float* bg    = (const float*)d_in[7];
    const float* bb    = (const float*)d_in[8];
    const float* fw    = (const float*)d_in[9];
    const float* fb    = (const float*)d_in[10];
    float* out = (float*)d_out;

    cudaFuncSetAttribute(k_mma, cudaFuncAttributeMaxDynamicSharedMemorySize, MMA_SMEM);

    // launch 0: fused setup (detect + embed + convert + cell-hist + prepack)
    k_setup<<<(N_NODES * C + 255) / 256, 256>>>(x, emb, ei, eattr, cw, cr, fw);
    // launch 1: node totals (parallel)
    k_sumcells<<<(N_NODES + 255) / 256, 256>>>();
    // launch 2: scan over node totals (re-zeroes g_cnt)
    k_scan<<<1, 1024>>>();
    // launch 3: per-node cell cursors (parallel; re-zeroes g_cnt2)
    k_cursors<<<(N_NODES + 255) / 256, 256>>>();
    // launch 4: cell-bucketed scatter (leaves g_cursor2 = per-cell end offsets)
    k_scatter<<<(N_EDGES + 255) / 256, 256>>>(eattr);

    const int mma_grid = (N_NODES + 127) / 128;  // 391
    for (int L = 0; L < 3; L++) {
        k_aggregate<<<N_NODES, 128>>>(L > 0 ? 1 : 0, L > 0 ? 1 : 0);
        k_mma<<<mma_grid, 256, MMA_SMEM>>>(L, cb + (size_t)L * C);
        k_bnfin<<<1, 128>>>(L, bg + (size_t)L * C, bb + (size_t)L * C);
    }

    k_gemm<<<(N_NODES + BMT - 1) / BMT, 256>>>(fb, out, C);
}

// round 16
// speedup vs baseline: 1.1134x; 1.1134x over previous
#include <cuda_runtime.h>
#include <cuda_bf16.h>
#include <stdint.h>
#include <cstdint>
#include <math.h>

#define N_NODES 50000
#define N_EDGES 1600000
#define C 128
#define KK 25            // 5x5 spline slots
#define KEXT 26          // + root slot
#define GK (KEXT * C)    // 3328
#define BN_EPS 1e-5f

// ---------------- device scratch (allocation-free: static globals) ----------------
__device__ float  g_h[(size_t)N_NODES * C];       // layer-0 input (embedded)
__device__ float  g_hpre[(size_t)N_NODES * C];    // pre-BN conv output
__device__ __nv_bfloat16 g_Ghi[(size_t)N_NODES * GK];  // gathered features hi plane
__device__ __nv_bfloat16 g_Glo[(size_t)N_NODES * GK];  // lo plane
__device__ int    g_src32[N_EDGES];
__device__ int    g_dst32[N_EDGES];
__device__ int    g_cnt[N_NODES];                 // node totals (k_sumcells -> k_scan)
__device__ int    g_cnt2[N_NODES * 16];           // per (node,cell); zero at load,
                                                  // re-zeroed by k_cursors each call
__device__ int    g_rowptr[N_NODES + 1];
__device__ int    g_cursor2[N_NODES * 16];
__device__ int    g_csr_src[N_EDGES];
__device__ float4 g_csr_w[N_EDGES];
__device__ int    g_csr_base[N_EDGES];
__device__ float  g_bnsum[3][C], g_bnsq[3][C];    // per-layer stats (zeroed in setup)
__device__ float  g_bna[C], g_bnb[C];             // current-layer affine
__device__ float  g_wt[C * C];                    // final_w transposed
// Pre-transposed + hi/lo split conv weights: [L][n][k] K-major bf16
__device__ __nv_bfloat16 g_wt_hi[3ull * C * GK];
__device__ __nv_bfloat16 g_wt_lo[3ull * C * GK];

__device__ __forceinline__ unsigned smem_u32(const void* p) {
    unsigned a;
    asm("{ .reg .u64 t; cvta.to.shared.u64 t, %1; cvt.u32.u64 %0, t; }" : "=r"(a) : "l"(p));
    return a;
}
__device__ __forceinline__ unsigned pack_bf16x2f(float x, float y) {
    __nv_bfloat16 hx = __float2bfloat16(x), hy = __float2bfloat16(y);
    return ((unsigned)__bfloat16_as_ushort(hy) << 16) | __bfloat16_as_ushort(hx);
}

// ---------------- fused setup: detect + embed + convert + cell-hist + prepack ----
__global__ void k_setup(const void* xp, const float* __restrict__ emb,
                        const void* eip, const float* __restrict__ attr,
                        const float* __restrict__ cw, const float* __restrict__ cr,
                        const float* __restrict__ fw) {
    int i = blockIdx.x * blockDim.x + threadIdx.x;

    // inline int64-vs-int32 detection (warp-uniform, L1-resident loads)
    int flag;
    {
        const int* e32 = (const int*)eip;
        int lane = threadIdx.x & 31;
        int z = 1;
        #pragma unroll
        for (int q = 0; q < 4; q++)
            if (e32[2 * (lane + q * 32) + 1] != 0) z = 0;
        flag = __all_sync(0xffffffffu, z);   // 1 => int64 indices
    }

    // h0 = emb[x]  (i < 6.4M dominates the grid)
    if (i < N_NODES * C) {
        int n = i >> 7, c = i & 127;
        int xv = flag ? (int)((const long long*)xp)[n] : ((const int*)xp)[n];
        g_h[i] = emb[xv * C + c];
    }
    // edge index conversion + (node,cell) histogram (g_cnt2 is zero at entry)
    if (i < N_EDGES) {
        int s, d;
        if (flag) {
            s = (int)((const long long*)eip)[i];
            d = (int)((const long long*)eip)[N_EDGES + i];
        } else {
            s = ((const int*)eip)[i];
            d = ((const int*)eip)[N_EDGES + i];
        }
        g_src32[i] = s;
        g_dst32[i] = d;
        float v0 = attr[2 * i] * 4.0f;
        float v1 = attr[2 * i + 1] * 4.0f;
        int l0 = (int)fminf(fmaxf(floorf(v0), 0.0f), 3.0f);
        int l1 = (int)fminf(fmaxf(floorf(v1), 0.0f), 3.0f);
        atomicAdd(&g_cnt2[d * 16 + l0 + 4 * l1], 1);
    }
    // zero BN stats
    if (i < 3 * C) { g_bnsum[i / C][i % C] = 0.0f; g_bnsq[i / C][i % C] = 0.0f; }
    // final_w transpose
    if (i < C * C) {
        int k = i >> 7, o = i & 127;
        g_wt[k * C + o] = fw[o * C + k];
    }
    // conv weight prepack: transpose + hi/lo bf16 split
    if (i < 3 * GK * C) {
        int L = i / (GK * C);
        int rem = i - L * (GK * C);
        int n = rem / GK;
        int k = rem - n * GK;
        float v = (k < KK * C) ? cw[(size_t)L * KK * C * C + (size_t)k * C + n]
                               : cr[(size_t)L * C * C + (size_t)(k - KK * C) * C + n];
        __nv_bfloat16 h = __float2bfloat16(v);
        __nv_bfloat16 l = __float2bfloat16(v - __bfloat162float(h));
        size_t o = (size_t)L * C * GK + (size_t)n * GK + k;
        g_wt_hi[o] = h;
        g_wt_lo[o] = l;
    }
}

// ---------------- parallel: node totals from 16-cell histogram ----------------
__global__ void k_sumcells() {
    int n = blockIdx.x * blockDim.x + threadIdx.x;
    if (n >= N_NODES) return;
    const int4* p = (const int4*)&g_cnt2[n * 16];
    int v = 0;
    #pragma unroll
    for (int q = 0; q < 4; q++) {
        int4 c4 = p[q];
        v += c4.x + c4.y + c4.z + c4.w;
    }
    g_cnt[n] = v;
}

// ---------------- CSR scan over node totals (single block); re-zeroes g_cnt ----
__global__ void k_scan() {  // single block, 1024 threads
    __shared__ int wsum[32];
    __shared__ int carry;
    int t = threadIdx.x;
    if (t == 0) carry = 0;
    __syncthreads();
    const int nchunks = (N_NODES + 1023) / 1024;
    for (int ch = 0; ch < nchunks; ch++) {
        int i = ch * 1024 + t;
        int v = 0;
        if (i < N_NODES) { v = g_cnt[i]; g_cnt[i] = 0; }
        int x = v;
        #pragma unroll
        for (int o = 1; o < 32; o <<= 1) {
            int y = __shfl_up_sync(0xffffffffu, x, o);
            if ((t & 31) >= o) x += y;
        }
        if ((t & 31) == 31) wsum[t >> 5] = x;
        __syncthreads();
        if (t < 32) {
            int w = wsum[t], xw = w;
            #pragma unroll
            for (int o = 1; o < 32; o <<= 1) {
                int y = __shfl_up_sync(0xffffffffu, xw, o);
                if (t >= o) xw += y;
            }
            wsum[t] = xw - w;  // exclusive warp offsets
        }
        __syncthreads();
        int incl = x + wsum[t >> 5] + carry;
        if (i < N_NODES) g_rowptr[i] = incl - v;
        __syncthreads();
        if (t == 1023) carry = incl;
        __syncthreads();
    }
    if (t == 0) g_rowptr[N_NODES] = carry;
}

// ---------------- parallel: per-node cell cursors; re-zeroes g_cnt2 ------------
__global__ void k_cursors() {
    int n = blockIdx.x * blockDim.x + threadIdx.x;
    if (n >= N_NODES) return;
    int base = g_rowptr[n];
    #pragma unroll
    for (int cell = 0; cell < 16; cell++) {
        int idx = n * 16 + cell;
        int cnt = g_cnt2[idx];
        g_cursor2[idx] = base;
        base += cnt;
        g_cnt2[idx] = 0;
    }
}

__global__ void k_scatter(const float* __restrict__ attr) {
    int e = blockIdx.x * blockDim.x + threadIdx.x;
    if (e >= N_EDGES) return;
    int d = g_dst32[e];
    float v0 = attr[2 * e] * 4.0f;
    float v1 = attr[2 * e + 1] * 4.0f;
    float l0 = fminf(fmaxf(floorf(v0), 0.0f), 3.0f);
    float l1 = fminf(fmaxf(floorf(v1), 0.0f), 3.0f);
    float f0 = v0 - l0, f1 = v1 - l1;
    int cell = (int)l0 + 4 * (int)l1;
    int pos = atomicAdd(&g_cursor2[d * 16 + cell], 1);
    g_csr_src[pos] = g_src32[e];
    float w00 = (1.0f - f0) * (1.0f - f1);
    float w10 = f0 * (1.0f - f1);
    float w01 = (1.0f - f0) * f1;
    float w11 = f0 * f1;
    g_csr_w[pos] = make_float4(w00, w10, w01, w11);
    g_csr_base[pos] = (int)l0 + 5 * (int)l1;
}

// ---------------- aggregation: cell-sorted run-accumulation + vector epilogue ----
__global__ void __launch_bounds__(128) k_aggregate(int use_bn, int relu) {
    const int n = blockIdx.x;
    const int c = threadIdx.x;
    __shared__ float acc[KEXT * C];  // 13 KB; rows 0..24 spline slots, row 25 root
    #pragma unroll
    for (int k = 0; k < KK; k++) acc[k * C + c] = 0.0f;

    float a = 1.0f, b = 0.0f;
    const float* in = g_h;
    if (use_bn) { a = g_bna[c]; b = g_bnb[c]; in = g_hpre; }

    const int rs = g_rowptr[n], re = g_rowptr[n + 1];
    float4 w_n = make_float4(0.f, 0.f, 0.f, 0.f);
    int bs_n = 0;
    float hr_n = 0.0f;
    if (rs < re) {
        int s = g_csr_src[rs];
        w_n = g_csr_w[rs];
        bs_n = g_csr_base[rs];
        hr_n = in[(size_t)s * C + c];
    }
    int cur = -1;
    float r0 = 0.f, r1 = 0.f, r2 = 0.f, r3 = 0.f;
    for (int e = rs; e < re; e++) {
        float4 w = w_n;
        int bs = bs_n;
        float hr = hr_n;
        int en = e + 1;
        if (en < re) {                       // prefetch next edge
            int s = g_csr_src[en];
            w_n = g_csr_w[en];
            bs_n = g_csr_base[en];
            hr_n = in[(size_t)s * C + c];
        }
        float hv = a * hr + b;
        if (relu) hv = fmaxf(hv, 0.0f);
        if (bs != cur) {                     // warp-uniform branch (one node/block)
            if (cur >= 0) {
                acc[cur * C + c]       += r0;
                acc[(cur + 1) * C + c] += r1;
                acc[(cur + 5) * C + c] += r2;
                acc[(cur + 6) * C + c] += r3;
            }
            cur = bs;
            r0 = w.x * hv; r1 = w.y * hv; r2 = w.z * hv; r3 = w.w * hv;
        } else {
            r0 += w.x * hv; r1 += w.y * hv; r2 += w.z * hv; r3 += w.w * hv;
        }
    }
    if (cur >= 0) {
        acc[cur * C + c]       += r0;
        acc[(cur + 1) * C + c] += r1;
        acc[(cur + 5) * C + c] += r2;
        acc[(cur + 6) * C + c] += r3;
    }
    // root row into smem row 25
    {
        float v = a * in[(size_t)n * C + c] + b;
        if (relu) v = fmaxf(v, 0.0f);
        acc[KK * C + c] = v;
    }
    __syncthreads();

    // ---- vectorized epilogue: lane handles 4 channels, LDS.128 + 2x STG.64 ----
    const float invd = 1.0f / fmaxf((float)(re - rs), 1.0f);
    const size_t gb = (size_t)n * GK;
    const int lane = c & 31;
    const int rgrp = c >> 5;                 // 0..3
    #pragma unroll
    for (int rb = 0; rb < 7; rb++) {
        int row = rb * 4 + rgrp;
        if (row < KEXT) {
            float4 v = *(const float4*)&acc[row * C + lane * 4];
            float m = (row < KK) ? invd : 1.0f;
            v.x *= m; v.y *= m; v.z *= m; v.w *= m;
            float hx = __bfloat162float(__float2bfloat16(v.x));
            float hy = __bfloat162float(__float2bfloat16(v.y));
            float hz = __bfloat162float(__float2bfloat16(v.z));
            float hw = __bfloat162float(__float2bfloat16(v.w));
            uint2 hp = make_uint2(pack_bf16x2f(v.x, v.y), pack_bf16x2f(v.z, v.w));
            uint2 lp = make_uint2(pack_bf16x2f(v.x - hx, v.y - hy),
                                  pack_bf16x2f(v.z - hz, v.w - hw));
            *(uint2*)(g_Ghi + gb + row * C + lane * 4) = hp;
            *(uint2*)(g_Glo + gb + row * C + lane * 4) = lp;
        }
    }
}

// ================= mma.sync bf16 hi/lo GEMM, cp.async 2-stage, fused BN stats ====
#define KCH 32                // K per chunk (bf16 elems)
#define NCH (GK / KCH)        // 104
#define SAS 40                // smem row stride in bf16 (80B)
#define PLANE (128 * SAS * 2) // 10240 B per plane
#define STAGE (4 * PLANE)     // Ah, Al, Bh, Bl
#define MMA_SMEM (2 * STAGE)  // 81920 B

__device__ __forceinline__ void cp16(unsigned dst, const void* src, int srcsize) {
    asm volatile("cp.async.cg.shared.global [%0], [%1], 16, %2;"
                 :: "r"(dst), "l"(src), "r"(srcsize) : "memory");
}
__device__ __forceinline__ void ldmx4(unsigned addr, unsigned* r) {
    asm volatile("ldmatrix.sync.aligned.m8n8.x4.shared.b16 {%0,%1,%2,%3}, [%4];"
                 : "=r"(r[0]), "=r"(r[1]), "=r"(r[2]), "=r"(r[3]) : "r"(addr));
}
__device__ __forceinline__ void mma16816(float* c, const unsigned* a,
                                         unsigned b0, unsigned b1) {
    asm volatile(
        "mma.sync.aligned.m16n8k16.row.col.f32.bf16.bf16.f32 "
        "{%0,%1,%2,%3}, {%4,%5,%6,%7}, {%8,%9}, {%0,%1,%2,%3};"
        : "+f"(c[0]), "+f"(c[1]), "+f"(c[2]), "+f"(c[3])
        : "r"(a[0]), "r"(a[1]), "r"(a[2]), "r"(a[3]), "r"(b0), "r"(b1));
}

__global__ void __launch_bounds__(256, 2) k_mma(int L, const float* __restrict__ bias) {
    extern __shared__ __align__(16) char dsm[];
    __shared__ float s_sum[C], s_sq[C];
    const unsigned sbase = smem_u32(dsm);
    const int tid = threadIdx.x;
    const int lid = tid & 31;
    const int w = tid >> 5;
    const int warp_m = (w & 3) * 32;
    const int warp_n = (w >> 2) * 64;
    const int mtile = blockIdx.x * 128;
    const char* ghi = (const char*)g_Ghi;
    const char* glo = (const char*)g_Glo;
    const char* wh = (const char*)(g_wt_hi + (size_t)L * C * GK);
    const char* wl = (const char*)(g_wt_lo + (size_t)L * C * GK);

    if (tid < C) { s_sum[tid] = 0.0f; s_sq[tid] = 0.0f; }

    const int row0 = tid >> 2, seg0 = (tid & 3) * 16;
    const int segk = (tid & 3) * 8;

    float acc[2][8][4];
    #pragma unroll
    for (int mi = 0; mi < 2; mi++)
        #pragma unroll
        for (int nb = 0; nb < 8; nb++)
            #pragma unroll
            for (int q = 0; q < 4; q++) acc[mi][nb][q] = 0.0f;

    auto issue = [&](int st, int ch) {
        unsigned sb = sbase + st * STAGE;
        size_t kb = (size_t)ch * KCH * 2;
        #pragma unroll
        for (int i = 0; i < 2; i++) {
            int row = row0 + i * 64;
            int gm = mtile + row;
            int ok = (gm < N_NODES) ? 16 : 0;
            size_t abyte = (size_t)(gm < N_NODES ? gm : 0) * (GK * 2) + kb + segk * 2;
            unsigned d = sb + row * (SAS * 2) + seg0;
            cp16(d, ghi + abyte, ok);
            cp16(d + PLANE, glo + abyte, ok);
            size_t bbyte = (size_t)row * (GK * 2) + kb + segk * 2;
            cp16(d + 2 * PLANE, wh + bbyte, 16);
            cp16(d + 3 * PLANE, wl + bbyte, 16);
        }
        asm volatile("cp.async.commit_group;" ::: "memory");
    };

    issue(0, 0);

    #pragma unroll 1
    for (int ch = 0; ch < NCH; ch++) {
        if (ch + 1 < NCH) {
            issue((ch + 1) & 1, ch + 1);
            asm volatile("cp.async.wait_group 1;" ::: "memory");
        } else {
            asm volatile("cp.async.wait_group 0;" ::: "memory");
        }
        __syncthreads();

        const unsigned ab = sbase + (ch & 1) * STAGE;
        #pragma unroll
        for (int kk = 0; kk < 2; kk++) {
            unsigned ah[2][4], al[2][4];
            #pragma unroll
            for (int mi = 0; mi < 2; mi++) {
                unsigned row = warp_m + mi * 16 + ((lid >> 3) & 1) * 8 + (lid & 7);
                unsigned col = kk * 16 + ((lid >> 4) & 1) * 8;
                unsigned off = (row * SAS + col) * 2;
                ldmx4(ab + off, ah[mi]);
                ldmx4(ab + PLANE + off, al[mi]);
            }
            #pragma unroll
            for (int nbp = 0; nbp < 4; nbp++) {
                unsigned nrow = warp_n + nbp * 16 + ((lid >> 4) & 1) * 8 + (lid & 7);
                unsigned col = kk * 16 + ((lid >> 3) & 1) * 8;
                unsigned off = (nrow * SAS + col) * 2;
                unsigned bh[4], bl[4];
                ldmx4(ab + 2 * PLANE + off, bh);
                ldmx4(ab + 3 * PLANE + off, bl);
                #pragma unroll
                for (int half = 0; half < 2; half++) {
                    int nb = nbp * 2 + half;
                    #pragma unroll
                    for (int mi = 0; mi < 2; mi++) {
                        mma16816(acc[mi][nb], ah[mi], bh[half * 2], bh[half * 2 + 1]);
                        mma16816(acc[mi][nb], ah[mi], bl[half * 2], bl[half * 2 + 1]);
                        mma16816(acc[mi][nb], al[mi], bh[half * 2], bh[half * 2 + 1]);
                    }
                }
            }
        }
        __syncthreads();
    }

    // ---- epilogue: write acc + bias to g_hpre, accumulate BN stats ----
    #pragma unroll
    for (int mi = 0; mi < 2; mi++) {
        int m0 = mtile + warp_m + mi * 16 + (lid >> 2);
        bool v0 = (m0 < N_NODES), v1 = (m0 + 8 < N_NODES);
        #pragma unroll
        for (int nb = 0; nb < 8; nb++) {
            int n = warp_n + nb * 8 + 2 * (lid & 3);
            float b0 = bias[n], b1 = bias[n + 1];
            float o00 = acc[mi][nb][0] + b0, o01 = acc[mi][nb][1] + b1;
            float o10 = acc[mi][nb][2] + b0, o11 = acc[mi][nb][3] + b1;
            float s0 = 0.f, s1 = 0.f, q0 = 0.f, q1 = 0.f;
            if (v0) {
                *(float2*)(g_hpre + (size_t)m0 * C + n) = make_float2(o00, o01);
                s0 += o00; s1 += o01; q0 += o00 * o00; q1 += o01 * o01;
            }
            if (v1) {
                *(float2*)(g_hpre + (size_t)(m0 + 8) * C + n) = make_float2(o10, o11);
                s0 += o10; s1 += o11; q0 += o10 * o10; q1 += o11 * o11;
            }
            atomicAdd(&s_sum[n], s0);
            atomicAdd(&s_sum[n + 1], s1);
            atomicAdd(&s_sq[n], q0);
            atomicAdd(&s_sq[n + 1], q1);
        }
    }
    __syncthreads();
    if (tid < C) {
        atomicAdd(&g_bnsum[L][tid], s_sum[tid]);
        atomicAdd(&g_bnsq[L][tid], s_sq[tid]);
    }
}

// ---------------- fp32 GEMM (final linear): out = BN(hpre) @ wt + bias ----------
#define BMT 128
#define BKT 8
__global__ void __launch_bounds__(256) k_gemm(const float* __restrict__ bias,
                                              float* outp, int K) {
    __shared__ __align__(16) float As[BKT][BMT];
    __shared__ __align__(16) float Bs[BKT][C];
    const float* A = g_hpre;
    float* Cp = outp;

    int tid = threadIdx.x;
    int mtile = blockIdx.x * BMT;
    int tr = tid >> 4;
    int tc = tid & 15;

    float acc[8][8];
    #pragma unroll
    for (int i = 0; i < 8; i++)
        #pragma unroll
        for (int j = 0; j < 8; j++) acc[i][j] = 0.0f;

    int arow = tid >> 1;
    int akp  = (tid & 1) * 4;
    int bkb  = tid >> 5;
    int bcol = (tid & 31) * 4;

    for (int k0 = 0; k0 < K; k0 += BKT) {
        {
            float4 av = make_float4(0.f, 0.f, 0.f, 0.f);
            int gm = mtile + arow;
            if (gm < N_NODES) {
                av = *(const float4*)(A + (size_t)gm * K + k0 + akp);
                float4 a4 = *(const float4*)(g_bna + k0 + akp);
                float4 b4 = *(const float4*)(g_bnb + k0 + akp);
                av.x = a4.x * av.x + b4.x;
                av.y = a4.y * av.y + b4.y;
                av.z = a4.z * av.z + b4.z;
                av.w = a4.w * av.w + b4.w;
            }
            As[akp][arow]     = av.x;
            As[akp + 1][arow] = av.y;
            As[akp + 2][arow] = av.z;
            As[akp + 3][arow] = av.w;
        }
        {
            int kg = k0 + bkb;
            *(float4*)&Bs[bkb][bcol] = *(const float4*)(&g_wt[(size_t)kg * C] + bcol);
        }
        __syncthreads();
        #pragma unroll
        for (int kk = 0; kk < BKT; kk++) {
            float4 a0 = *(float4*)&As[kk][tr * 8];
            float4 a1 = *(float4*)&As[kk][tr * 8 + 4];
            float4 b0 = *(float4*)&Bs[kk][tc * 8];
            float4 b1 = *(float4*)&Bs[kk][tc * 8 + 4];
            float av[8] = {a0.x, a0.y, a0.z, a0.w, a1.x, a1.y, a1.z, a1.w};
            float bv[8] = {b0.x, b0.y, b0.z, b0.w, b1.x, b1.y, b1.z, b1.w};
            #pragma unroll
            for (int i = 0; i < 8; i++)
                #pragma unroll
                for (int j = 0; j < 8; j++) acc[i][j] += av[i] * bv[j];
        }
        __syncthreads();
    }

    float bv[8];
    #pragma unroll
    for (int j = 0; j < 8; j++) bv[j] = bias[tc * 8 + j];
    #pragma unroll
    for (int i = 0; i < 8; i++) {
        int gm = mtile + tr * 8 + i;
        if (gm < N_NODES) {
            float4 o0 = make_float4(acc[i][0] + bv[0], acc[i][1] + bv[1],
                                    acc[i][2] + bv[2], acc[i][3] + bv[3]);
            float4 o1 = make_float4(acc[i][4] + bv[4], acc[i][5] + bv[5],
                                    acc[i][6] + bv[6], acc[i][7] + bv[7]);
            *(float4*)(Cp + (size_t)gm * C + tc * 8)     = o0;
            *(float4*)(Cp + (size_t)gm * C + tc * 8 + 4) = o1;
        }
    }
}

// ---------------- batch norm finalize ----------------
__global__ void k_bnfin(int L, const float* __restrict__ gamma,
                        const float* __restrict__ beta) {
    int c = threadIdx.x;
    if (c >= C) return;
    float mu = g_bnsum[L][c] / (float)N_NODES;
    float var = fmaxf(g_bnsq[L][c] / (float)N_NODES - mu * mu, 0.0f);
    float a = gamma[c] * rsqrtf(var + BN_EPS);
    g_bna[c] = a;
    g_bnb[c] = beta[c] - a * mu;
}

// ---------------- launch ----------------
extern "C" void kernel_launch(void* const* d_in, const int* in_sizes, int n_in,
                              void* d_out, int out_size) {
    const void*  x     = d_in[0];
    const void*  ei    = d_in[1];
    const float* eattr = (const float*)d_in[2];
    const float* emb   = (const float*)d_in[3];
    const float* cw    = (const float*)d_in[4];   // [3,25,128,128]
    const float* cr    = (const float*)d_in[5];   // [3,128,128]
    const float* cb    = (const float*)d_in[6];   // [3,128]
    const float* bg    = (const float*)d_in[7];
    const float* bb    = (const float*)d_in[8];
    const float* fw    = (const float*)d_in[9];
    const float* fb    = (const float*)d_in[10];
    float* out = (float*)d_out;

    cudaFuncSetAttribute(k_mma, cudaFuncAttributeMaxDynamicSharedMemorySize, MMA_SMEM);

    // launch 0: fused setup (detect + embed + convert + cell-hist + prepack)
    k_setup<<<(N_NODES * C + 255) / 256, 256>>>(x, emb, ei, eattr, cw, cr, fw);
    // launch 1: node totals (parallel)
    k_sumcells<<<(N_NODES + 255) / 256, 256>>>();
    // launch 2: scan over node totals (re-zeroes g_cnt)
    k_scan<<<1, 1024>>>();
    // launch 3: per-node cell cursors (parallel; re-zeroes g_cnt2)
    k_cursors<<<(N_NODES + 255) / 256, 256>>>();
    // launch 4: cell-bucketed scatter
    k_scatter<<<(N_EDGES + 255) / 256, 256>>>(eattr);

    const int mma_grid = (N_NODES + 127) / 128;  // 391
    for (int L = 0; L < 3; L++) {
        k_aggregate<<<N_NODES, 128>>>(L > 0 ? 1 : 0, L > 0 ? 1 : 0);
        k_mma<<<mma_grid, 256, MMA_SMEM>>>(L, cb + (size_t)L * C);
        k_bnfin<<<1, 128>>>(L, bg + (size_t)L * C, bb + (size_t)L * C);
    }

    k_gemm<<<(N_NODES + BMT - 1) / BMT, 256>>>(fb, out, C);
}

// round 17
// speedup vs baseline: 1.1831x; 1.0626x over previous
#include <cuda_runtime.h>
#include <cuda_bf16.h>
#include <stdint.h>
#include <cstdint>
#include <math.h>

#define N_NODES 50000
#define N_EDGES 1600000
#define C 128
#define KK 25            // 5x5 spline slots
#define KEXT 26          // + root slot
#define GK (KEXT * C)    // 3328
#define BN_EPS 1e-5f

// ---------------- device scratch (allocation-free: static globals) ----------------
__device__ float  g_h[(size_t)N_NODES * C];       // layer-0 input (embedded)
__device__ float  g_hpre[(size_t)N_NODES * C];    // pre-BN conv output
__device__ __nv_bfloat16 g_Ghi[(size_t)N_NODES * GK];  // gathered features hi plane
__device__ __nv_bfloat16 g_Glo[(size_t)N_NODES * GK];  // lo plane
__device__ int    g_src32[N_EDGES];
__device__ int    g_dst32[N_EDGES];
__device__ int    g_cnt[N_NODES];                 // node totals (k_sumcells -> k_scan)
__device__ int    g_cnt2[N_NODES * 16];           // per (node,cell); zero at load,
                                                  // re-zeroed by k_cursors each call
__device__ int    g_rowptr[N_NODES + 1];
__device__ int    g_cursor2[N_NODES * 16];
__device__ int    g_csr_src[N_EDGES];             // packed: (cell_base << 16) | src
__device__ float4 g_csr_w[N_EDGES];
__device__ float  g_bnsum[3][C], g_bnsq[3][C];    // per-layer stats (zeroed in setup)
__device__ float  g_bna[C], g_bnb[C];             // current-layer affine
// Pre-transposed + hi/lo split conv weights: [L][n][k] K-major bf16
__device__ __nv_bfloat16 g_wt_hi[3ull * C * GK];
__device__ __nv_bfloat16 g_wt_lo[3ull * C * GK];
// final_w hi/lo (already K-major: out[m,n] = sum_k h[m,k]*fw[n,k])
__device__ __nv_bfloat16 g_fw_hi[C * C];
__device__ __nv_bfloat16 g_fw_lo[C * C];

__device__ __forceinline__ unsigned smem_u32(const void* p) {
    unsigned a;
    asm("{ .reg .u64 t; cvta.to.shared.u64 t, %1; cvt.u32.u64 %0, t; }" : "=r"(a) : "l"(p));
    return a;
}
__device__ __forceinline__ unsigned pack_bf16x2f(float x, float y) {
    __nv_bfloat16 hx = __float2bfloat16(x), hy = __float2bfloat16(y);
    return ((unsigned)__bfloat16_as_ushort(hy) << 16) | __bfloat16_as_ushort(hx);
}

// ---------------- fused setup: detect + embed + convert + cell-hist + prepack ----
__global__ void k_setup(const void* xp, const float* __restrict__ emb,
                        const void* eip, const float* __restrict__ attr,
                        const float* __restrict__ cw, const float* __restrict__ cr,
                        const float* __restrict__ fw) {
    int i = blockIdx.x * blockDim.x + threadIdx.x;

    // inline int64-vs-int32 detection (warp-uniform, L1-resident loads)
    int flag;
    {
        const int* e32 = (const int*)eip;
        int lane = threadIdx.x & 31;
        int z = 1;
        #pragma unroll
        for (int q = 0; q < 4; q++)
            if (e32[2 * (lane + q * 32) + 1] != 0) z = 0;
        flag = __all_sync(0xffffffffu, z);   // 1 => int64 indices
    }

    // h0 = emb[x]  (i < 6.4M dominates the grid)
    if (i < N_NODES * C) {
        int n = i >> 7, c = i & 127;
        int xv = flag ? (int)((const long long*)xp)[n] : ((const int*)xp)[n];
        g_h[i] = emb[xv * C + c];
    }
    // edge index conversion + (node,cell) histogram (g_cnt2 is zero at entry)
    if (i < N_EDGES) {
        int s, d;
        if (flag) {
            s = (int)((const long long*)eip)[i];
            d = (int)((const long long*)eip)[N_EDGES + i];
        } else {
            s = ((const int*)eip)[i];
            d = ((const int*)eip)[N_EDGES + i];
        }
        g_src32[i] = s;
        g_dst32[i] = d;
        float v0 = attr[2 * i] * 4.0f;
        float v1 = attr[2 * i + 1] * 4.0f;
        int l0 = (int)fminf(fmaxf(floorf(v0), 0.0f), 3.0f);
        int l1 = (int)fminf(fmaxf(floorf(v1), 0.0f), 3.0f);
        atomicAdd(&g_cnt2[d * 16 + l0 + 4 * l1], 1);
    }
    // zero BN stats
    if (i < 3 * C) { g_bnsum[i / C][i % C] = 0.0f; g_bnsq[i / C][i % C] = 0.0f; }
    // final_w hi/lo prepack (already K-major)
    if (i < C * C) {
        float v = fw[i];
        __nv_bfloat16 h = __float2bfloat16(v);
        g_fw_hi[i] = h;
        g_fw_lo[i] = __float2bfloat16(v - __bfloat162float(h));
    }
    // conv weight prepack: transpose + hi/lo bf16 split
    if (i < 3 * GK * C) {
        int L = i / (GK * C);
        int rem = i - L * (GK * C);
        int n = rem / GK;
        int k = rem - n * GK;
        float v = (k < KK * C) ? cw[(size_t)L * KK * C * C + (size_t)k * C + n]
                               : cr[(size_t)L * C * C + (size_t)(k - KK * C) * C + n];
        __nv_bfloat16 h = __float2bfloat16(v);
        __nv_bfloat16 l = __float2bfloat16(v - __bfloat162float(h));
        size_t o = (size_t)L * C * GK + (size_t)n * GK + k;
        g_wt_hi[o] = h;
        g_wt_lo[o] = l;
    }
}

// ---------------- parallel: node totals from 16-cell histogram ----------------
__global__ void k_sumcells() {
    int n = blockIdx.x * blockDim.x + threadIdx.x;
    if (n >= N_NODES) return;
    const int4* p = (const int4*)&g_cnt2[n * 16];
    int v = 0;
    #pragma unroll
    for (int q = 0; q < 4; q++) {
        int4 c4 = p[q];
        v += c4.x + c4.y + c4.z + c4.w;
    }
    g_cnt[n] = v;
}

// ---------------- CSR scan over node totals (single block); re-zeroes g_cnt ----
__global__ void k_scan() {  // single block, 1024 threads
    __shared__ int wsum[32];
    __shared__ int carry;
    int t = threadIdx.x;
    if (t == 0) carry = 0;
    __syncthreads();
    const int nchunks = (N_NODES + 1023) / 1024;
    for (int ch = 0; ch < nchunks; ch++) {
        int i = ch * 1024 + t;
        int v = 0;
        if (i < N_NODES) { v = g_cnt[i]; g_cnt[i] = 0; }
        int x = v;
        #pragma unroll
        for (int o = 1; o < 32; o <<= 1) {
            int y = __shfl_up_sync(0xffffffffu, x, o);
            if ((t & 31) >= o) x += y;
        }
        if ((t & 31) == 31) wsum[t >> 5] = x;
        __syncthreads();
        if (t < 32) {
            int w = wsum[t], xw = w;
            #pragma unroll
            for (int o = 1; o < 32; o <<= 1) {
                int y = __shfl_up_sync(0xffffffffu, xw, o);
                if (t >= o) xw += y;
            }
            wsum[t] = xw - w;  // exclusive warp offsets
        }
        __syncthreads();
        int incl = x + wsum[t >> 5] + carry;
        if (i < N_NODES) g_rowptr[i] = incl - v;
        __syncthreads();
        if (t == 1023) carry = incl;
        __syncthreads();
    }
    if (t == 0) g_rowptr[N_NODES] = carry;
}

// ---------------- parallel: per-node cell cursors; re-zeroes g_cnt2 ------------
__global__ void k_cursors() {
    int n = blockIdx.x * blockDim.x + threadIdx.x;
    if (n >= N_NODES) return;
    int base = g_rowptr[n];
    #pragma unroll
    for (int cell = 0; cell < 16; cell++) {
        int idx = n * 16 + cell;
        int cnt = g_cnt2[idx];
        g_cursor2[idx] = base;
        base += cnt;
        g_cnt2[idx] = 0;
    }
}

__global__ void k_scatter(const float* __restrict__ attr) {
    int e = blockIdx.x * blockDim.x + threadIdx.x;
    if (e >= N_EDGES) return;
    int d = g_dst32[e];
    float v0 = attr[2 * e] * 4.0f;
    float v1 = attr[2 * e + 1] * 4.0f;
    float l0 = fminf(fmaxf(floorf(v0), 0.0f), 3.0f);
    float l1 = fminf(fmaxf(floorf(v1), 0.0f), 3.0f);
    float f0 = v0 - l0, f1 = v1 - l1;
    int cell = (int)l0 + 4 * (int)l1;
    int pos = atomicAdd(&g_cursor2[d * 16 + cell], 1);
    int base = (int)l0 + 5 * (int)l1;
    g_csr_src[pos] = g_src32[e] | (base << 16);   // src < 2^16, base < 25
    float w00 = (1.0f - f0) * (1.0f - f1);
    float w10 = f0 * (1.0f - f1);
    float w01 = (1.0f - f0) * f1;
    float w11 = f0 * f1;
    g_csr_w[pos] = make_float4(w00, w10, w01, w11);
}

// ---------------- aggregation: cell-sorted run-accumulation + vector epilogue ----
__global__ void __launch_bounds__(128) k_aggregate(int use_bn, int relu) {
    const int n = blockIdx.x;
    const int c = threadIdx.x;
    __shared__ float acc[KEXT * C];  // 13 KB; rows 0..24 spline slots, row 25 root
    #pragma unroll
    for (int k = 0; k < KK; k++) acc[k * C + c] = 0.0f;

    float a = 1.0f, b = 0.0f;
    const float* in = g_h;
    if (use_bn) { a = g_bna[c]; b = g_bnb[c]; in = g_hpre; }

    const int rs = g_rowptr[n], re = g_rowptr[n + 1];
    float4 w_n = make_float4(0.f, 0.f, 0.f, 0.f);
    int p_n = 0;
    float hr_n = 0.0f;
    if (rs < re) {
        p_n = g_csr_src[rs];
        w_n = g_csr_w[rs];
        hr_n = in[(size_t)(p_n & 0xFFFF) * C + c];
    }
    int cur = -1;
    float r0 = 0.f, r1 = 0.f, r2 = 0.f, r3 = 0.f;
    for (int e = rs; e < re; e++) {
        float4 w = w_n;
        int bs = p_n >> 16;
        float hr = hr_n;
        int en = e + 1;
        if (en < re) {                       // prefetch next edge
            p_n = g_csr_src[en];
            w_n = g_csr_w[en];
            hr_n = in[(size_t)(p_n & 0xFFFF) * C + c];
        }
        float hv = a * hr + b;
        if (relu) hv = fmaxf(hv, 0.0f);
        if (bs != cur) {                     // warp-uniform branch (one node/block)
            if (cur >= 0) {
                acc[cur * C + c]       += r0;
                acc[(cur + 1) * C + c] += r1;
                acc[(cur + 5) * C + c] += r2;
                acc[(cur + 6) * C + c] += r3;
            }
            cur = bs;
            r0 = w.x * hv; r1 = w.y * hv; r2 = w.z * hv; r3 = w.w * hv;
        } else {
            r0 += w.x * hv; r1 += w.y * hv; r2 += w.z * hv; r3 += w.w * hv;
        }
    }
    if (cur >= 0) {
        acc[cur * C + c]       += r0;
        acc[(cur + 1) * C + c] += r1;
        acc[(cur + 5) * C + c] += r2;
        acc[(cur + 6) * C + c] += r3;
    }
    // root row into smem row 25
    {
        float v = a * in[(size_t)n * C + c] + b;
        if (relu) v = fmaxf(v, 0.0f);
        acc[KK * C + c] = v;
    }
    __syncthreads();

    // ---- vectorized epilogue: lane handles 4 channels, LDS.128 + 2x STG.64 ----
    const float invd = 1.0f / fmaxf((float)(re - rs), 1.0f);
    const size_t gb = (size_t)n * GK;
    const int lane = c & 31;
    const int rgrp = c >> 5;                 // 0..3
    #pragma unroll
    for (int rb = 0; rb < 7; rb++) {
        int row = rb * 4 + rgrp;
        if (row < KEXT) {
            float4 v = *(const float4*)&acc[row * C + lane * 4];
            float m = (row < KK) ? invd : 1.0f;
            v.x *= m; v.y *= m; v.z *= m; v.w *= m;
            float hx = __bfloat162float(__float2bfloat16(v.x));
            float hy = __bfloat162float(__float2bfloat16(v.y));
            float hz = __bfloat162float(__float2bfloat16(v.z));
            float hw = __bfloat162float(__float2bfloat16(v.w));
            uint2 hp = make_uint2(pack_bf16x2f(v.x, v.y), pack_bf16x2f(v.z, v.w));
            uint2 lp = make_uint2(pack_bf16x2f(v.x - hx, v.y - hy),
                                  pack_bf16x2f(v.z - hz, v.w - hw));
            *(uint2*)(g_Ghi + gb + row * C + lane * 4) = hp;
            *(uint2*)(g_Glo + gb + row * C + lane * 4) = lp;
        }
    }
}

// ================= mma.sync bf16 hi/lo GEMM, cp.async 2-stage, fused BN stats ====
#define KCH 32                // K per chunk (bf16 elems)
#define NCH (GK / KCH)        // 104
#define SAS 40                // smem row stride in bf16 (80B)
#define PLANE (128 * SAS * 2) // 10240 B per plane
#define STAGE (4 * PLANE)     // Ah, Al, Bh, Bl
#define MMA_SMEM (2 * STAGE)  // 81920 B

__device__ __forceinline__ void cp16(unsigned dst, const void* src, int srcsize) {
    asm volatile("cp.async.cg.shared.global [%0], [%1], 16, %2;"
                 :: "r"(dst), "l"(src), "r"(srcsize) : "memory");
}
__device__ __forceinline__ void ldmx4(unsigned addr, unsigned* r) {
    asm volatile("ldmatrix.sync.aligned.m8n8.x4.shared.b16 {%0,%1,%2,%3}, [%4];"
                 : "=r"(r[0]), "=r"(r[1]), "=r"(r[2]), "=r"(r[3]) : "r"(addr));
}
__device__ __forceinline__ void mma16816(float* c, const unsigned* a,
                                         unsigned b0, unsigned b1) {
    asm volatile(
        "mma.sync.aligned.m16n8k16.row.col.f32.bf16.bf16.f32 "
        "{%0,%1,%2,%3}, {%4,%5,%6,%7}, {%8,%9}, {%0,%1,%2,%3};"
        : "+f"(c[0]), "+f"(c[1]), "+f"(c[2]), "+f"(c[3])
        : "r"(a[0]), "r"(a[1]), "r"(a[2]), "r"(a[3]), "r"(b0), "r"(b1));
}

// KTOT: total K of the GEMM; Ahi/Alo row stride = KTOT elems; Bhi/Blo same.
// stats: accumulate BN statistics; outp: destination (fp32, row stride C).
__device__ __forceinline__ void mma_body(
    const __nv_bfloat16* Ahi, const __nv_bfloat16* Alo,
    const __nv_bfloat16* Bhi, const __nv_bfloat16* Blo,
    int KTOT, const float* bias, float* outp, int L, int stats, char* dsm) {
    __shared__ float s_sum[C], s_sq[C];
    const unsigned sbase = smem_u32(dsm);
    const int tid = threadIdx.x;
    const int lid = tid & 31;
    const int w = tid >> 5;
    const int warp_m = (w & 3) * 32;
    const int warp_n = (w >> 2) * 64;
    const int mtile = blockIdx.x * 128;
    const int nch = KTOT / KCH;

    if (stats && tid < C) { s_sum[tid] = 0.0f; s_sq[tid] = 0.0f; }

    const int row0 = tid >> 2, seg0 = (tid & 3) * 16;
    const int segk = (tid & 3) * 8;

    float acc[2][8][4];
    #pragma unroll
    for (int mi = 0; mi < 2; mi++)
        #pragma unroll
        for (int nb = 0; nb < 8; nb++)
            #pragma unroll
            for (int q = 0; q < 4; q++) acc[mi][nb][q] = 0.0f;

    auto issue = [&](int st, int ch) {
        unsigned sb = sbase + st * STAGE;
        size_t kb = (size_t)ch * KCH;
        #pragma unroll
        for (int i = 0; i < 2; i++) {
            int row = row0 + i * 64;
            int gm = mtile + row;
            int ok = (gm < N_NODES) ? 16 : 0;
            size_t aoff = (size_t)(gm < N_NODES ? gm : 0) * KTOT + kb + segk;
            unsigned d = sb + row * (SAS * 2) + seg0;
            cp16(d, Ahi + aoff, ok);
            cp16(d + PLANE, Alo + aoff, ok);
            size_t boff = (size_t)row * KTOT + kb + segk;
            cp16(d + 2 * PLANE, Bhi + boff, 16);
            cp16(d + 3 * PLANE, Blo + boff, 16);
        }
        asm volatile("cp.async.commit_group;" ::: "memory");
    };

    issue(0, 0);

    #pragma unroll 1
    for (int ch = 0; ch < nch; ch++) {
        if (ch + 1 < nch) {
            issue((ch + 1) & 1, ch + 1);
            asm volatile("cp.async.wait_group 1;" ::: "memory");
        } else {
            asm volatile("cp.async.wait_group 0;" ::: "memory");
        }
        __syncthreads();

        const unsigned ab = sbase + (ch & 1) * STAGE;
        #pragma unroll
        for (int kk = 0; kk < 2; kk++) {
            unsigned ah[2][4], al[2][4];
            #pragma unroll
            for (int mi = 0; mi < 2; mi++) {
                unsigned row = warp_m + mi * 16 + ((lid >> 3) & 1) * 8 + (lid & 7);
                unsigned col = kk * 16 + ((lid >> 4) & 1) * 8;
                unsigned off = (row * SAS + col) * 2;
                ldmx4(ab + off, ah[mi]);
                ldmx4(ab + PLANE + off, al[mi]);
            }
            #pragma unroll
            for (int nbp = 0; nbp < 4; nbp++) {
                unsigned nrow = warp_n + nbp * 16 + ((lid >> 4) & 1) * 8 + (lid & 7);
                unsigned col = kk * 16 + ((lid >> 3) & 1) * 8;
                unsigned off = (nrow * SAS + col) * 2;
                unsigned bh[4], bl[4];
                ldmx4(ab + 2 * PLANE + off, bh);
                ldmx4(ab + 3 * PLANE + off, bl);
                #pragma unroll
                for (int half = 0; half < 2; half++) {
                    int nb = nbp * 2 + half;
                    #pragma unroll
                    for (int mi = 0; mi < 2; mi++) {
                        mma16816(acc[mi][nb], ah[mi], bh[half * 2], bh[half * 2 + 1]);
                        mma16816(acc[mi][nb], ah[mi], bl[half * 2], bl[half * 2 + 1]);
                        mma16816(acc[mi][nb], al[mi], bh[half * 2], bh[half * 2 + 1]);
                    }
                }
            }
        }
        __syncthreads();
    }

    // ---- epilogue: write acc + bias, optionally accumulate BN stats ----
    #pragma unroll
    for (int mi = 0; mi < 2; mi++) {
        int m0 = mtile + warp_m + mi * 16 + (lid >> 2);
        bool v0 = (m0 < N_NODES), v1 = (m0 + 8 < N_NODES);
        #pragma unroll
        for (int nb = 0; nb < 8; nb++) {
            int n = warp_n + nb * 8 + 2 * (lid & 3);
            float b0 = bias[n], b1 = bias[n + 1];
            float o00 = acc[mi][nb][0] + b0, o01 = acc[mi][nb][1] + b1;
            float o10 = acc[mi][nb][2] + b0, o11 = acc[mi][nb][3] + b1;
            float s0 = 0.f, s1 = 0.f, q0 = 0.f, q1 = 0.f;
            if (v0) {
                *(float2*)(outp + (size_t)m0 * C + n) = make_float2(o00, o01);
                s0 += o00; s1 += o01; q0 += o00 * o00; q1 += o01 * o01;
            }
            if (v1) {
                *(float2*)(outp + (size_t)(m0 + 8) * C + n) = make_float2(o10, o11);
                s0 += o10; s1 += o11; q0 += o10 * o10; q1 += o11 * o11;
            }
            if (stats) {
                atomicAdd(&s_sum[n], s0);
                atomicAdd(&s_sum[n + 1], s1);
                atomicAdd(&s_sq[n], q0);
                atomicAdd(&s_sq[n + 1], q1);
            }
        }
    }
    if (stats) {
        __syncthreads();
        if (tid < C) {
            atomicAdd(&g_bnsum[L][tid], s_sum[tid]);
            atomicAdd(&g_bnsq[L][tid], s_sq[tid]);
        }
    }
}

__global__ void __launch_bounds__(256, 2) k_mma(int L, const float* __restrict__ bias) {
    extern __shared__ __align__(16) char dsm[];
    mma_body(g_Ghi, g_Glo,
             g_wt_hi + (size_t)L * C * GK, g_wt_lo + (size_t)L * C * GK,
             GK, bias, g_hpre, L, 1, dsm);
}

// ---------------- final: convert BN(hpre) to hi/lo planes (K=128 layout) -------
__global__ void k_prep_final() {
    int i = blockIdx.x * blockDim.x + threadIdx.x;
    if (i >= N_NODES * C) return;
    int c = i & 127;
    float v = g_bna[c] * g_hpre[i] + g_bnb[c];   // last BN, no relu
    __nv_bfloat16 h = __float2bfloat16(v);
    g_Ghi[i] = h;
    g_Glo[i] = __float2bfloat16(v - __bfloat162float(h));
}

__global__ void __launch_bounds__(256, 2) k_fgemm(const float* __restrict__ bias,
                                                  float* outp) {
    extern __shared__ __align__(16) char dsm[];
    mma_body(g_Ghi, g_Glo, g_fw_hi, g_fw_lo, C, bias, outp, 0, 0, dsm);
}

// ---------------- batch norm finalize ----------------
__global__ void k_bnfin(int L, const float* __restrict__ gamma,
                        const float* __restrict__ beta) {
    int c = threadIdx.x;
    if (c >= C) return;
    float mu = g_bnsum[L][c] / (float)N_NODES;
    float var = fmaxf(g_bnsq[L][c] / (float)N_NODES - mu * mu, 0.0f);
    float a = gamma[c] * rsqrtf(var + BN_EPS);
    g_bna[c] = a;
    g_bnb[c] = beta[c] - a * mu;
}

// ---------------- launch ----------------
extern "C" void kernel_launch(void* const* d_in, const int* in_sizes, int n_in,
                              void* d_out, int out_size) {
    const void*  x     = d_in[0];
    const void*  ei    = d_in[1];
    const float* eattr = (const float*)d_in[2];
    const float* emb   = (const float*)d_in[3];
    const float* cw    = (const float*)d_in[4];   // [3,25,128,128]
    const float* cr    = (const float*)d_in[5];   // [3,128,128]
    const float* cb    = (const float*)d_in[6];   // [3,128]
    const float* bg    = (const float*)d_in[7];
    const float* bb    = (const float*)d_in[8];
    const float* fw    = (const float*)d_in[9];
    const float* fb    = (const float*)d_in[10];
    float* out = (float*)d_out;

    cudaFuncSetAttribute(k_mma, cudaFuncAttributeMaxDynamicSharedMemorySize, MMA_SMEM);
    cudaFuncSetAttribute(k_fgemm, cudaFuncAttributeMaxDynamicSharedMemorySize, MMA_SMEM);

    // launch 0: fused setup (detect + embed + convert + cell-hist + prepack)
    k_setup<<<(N_NODES * C + 255) / 256, 256>>>(x, emb, ei, eattr, cw, cr, fw);
    // launch 1: node totals (parallel)
    k_sumcells<<<(N_NODES + 255) / 256, 256>>>();
    // launch 2: scan over node totals (re-zeroes g_cnt)
    k_scan<<<1, 1024>>>();
    // launch 3: per-node cell cursors (parallel; re-zeroes g_cnt2)
    k_cursors<<<(N_NODES + 255) / 256, 256>>>();
    // launch 4: cell-bucketed scatter (packs cell base into src word)
    k_scatter<<<(N_EDGES + 255) / 256, 256>>>(eattr);

    const int mma_grid = (N_NODES + 127) / 128;  // 391
    for (int L = 0; L < 3; L++) {
        k_aggregate<<<N_NODES, 128>>>(L > 0 ? 1 : 0, L > 0 ? 1 : 0);
        k_mma<<<mma_grid, 256, MMA_SMEM>>>(L, cb + (size_t)L * C);
        k_bnfin<<<1, 128>>>(L, bg + (size_t)L * C, bb + (size_t)L * C);
    }

    // final linear via the same bf16 hi/lo mma machinery (K = 128)
    k_prep_final<<<(N_NODES * C + 255) / 256, 256>>>();
    k_fgemm<<<mma_grid, 256, MMA_SMEM>>>(fb, out);
}